// round 11
// baseline (speedup 1.0000x reference)
#include <cuda_runtime.h>
#include <cuda_bf16.h>

#define EE 1024
#define BB 256
#define DIN 784
#define DH 400
#define DOUT 10
#define NT_A 416
#define PF 4
#define CAP_E 32768        // stream entries per sample (expected ~7000)
#define CEVT 64            // entries per l2 chunk

// Static device scratch (no cudaMalloc allowed)
__device__ float g_W1T[DIN * DH + 32];             // transposed W1 (+pad)
__device__ float g_W2r[(DH + 1) * DOUT];           // [401][10], row 400 = 0
__device__ float g_ms[(size_t)BB * CAP_E];         // stream: multiplier
__device__ unsigned short g_js[(size_t)BB * CAP_E];// stream: weight-row index
__device__ unsigned g_tot[BB];                     // padded stream length (or ~0 = overflow)
__device__ unsigned g_maskov[BB][EE][13];          // masks (overflow fallback only)

__global__ void prep_kernel(const float* __restrict__ W1,
                            const float* __restrict__ W2,
                            const float* __restrict__ b2) {
    int idx = blockIdx.x * blockDim.x + threadIdx.x;
    if (idx < DIN * DH) {
        int p = idx / DH;
        int j = idx - p * DH;
        g_W1T[idx] = W1[j * DIN + p];
    } else if (idx < DIN * DH + (DH + 1) * DOUT) {
        int i = idx - DIN * DH;
        int j = i / DOUT;
        int d = i - j * DOUT;
        g_W2r[i] = (j < DH)
            ? __fadd_rn(W2[d * DH + j], __fdiv_rn(b2[d], 400.0f))
            : 0.0f;
    }
}

#define A_SMEM ((EE + PF) * 8 + EE * 13 * 4 + EE * 4 * 3 + 32)

// Layer 1: one CTA/sample, 13 warps, depth-4 register prefetch, no barriers
// in main loop. Epilogue emits the uniform (m, j) FFMA stream.
__global__ __launch_bounds__(NT_A, 2) void l1_kernel(
    const float* __restrict__ times,
    const int*   __restrict__ pix,
    const float* __restrict__ b1)
{
    extern __shared__ unsigned char dyn[];
    float2*   s_ev   = (float2*)dyn;                   // [EE+PF] (decay1, byteoff)
    unsigned* s_mask = (unsigned*)(s_ev + EE + PF);    // [EE][13]
    float*    s_d2   = (float*)(s_mask + EE * 13);     // [EE]
    unsigned* s_ent  = (unsigned*)(s_d2 + EE);         // [EE] entries per event
    unsigned* s_off  = s_ent + EE;                     // [EE] exclusive prefix
    unsigned* s_T    = s_off + EE;                     // [1]

    const float TAUF = 0.6213349345596119f;  // float(-1/ln(0.2))
    const int b    = blockIdx.x;
    const int tid  = threadIdx.x;
    const int warp = tid >> 5;
    const int lane = tid & 31;

    for (int e = tid; e < EE; e += NT_A) {
        float t  = times[b * EE + e];
        float tp = (e > 0) ? times[b * EE + e - 1] : 0.0f;
        float d1 = expf(__fdiv_rn(-(t - tp), TAUF));
        float th  = __fadd_rn(t, 0.1f);
        float thp = (e > 0) ? __fadd_rn(tp, 0.1f) : 0.0f;
        s_d2[e] = expf(__fdiv_rn(-(th - thp), TAUF));
        int p = pix[b * EE + e];
        s_ev[e] = make_float2(d1, __int_as_float(p * (DH * 4)));
    }
    if (tid < PF) s_ev[EE + tid] = make_float2(1.0f, __int_as_float(0));
    __syncthreads();

    const bool valid = (tid < DH);
    float h1 = 0.0f;
    float bias1j = valid ? __fdiv_rn(b1[tid], 784.0f) : 0.0f;
    const char* w1b = (const char*)g_W1T + tid * 4;

    float wbuf[PF], dbuf[PF];
    #pragma unroll
    for (int i = 0; i < PF; ++i) {
        float2 ev = s_ev[i];
        dbuf[i] = ev.x;
        wbuf[i] = *(const float*)(w1b + __float_as_int(ev.y));
    }

    for (int e = 0; e < EE; e += PF) {
        #pragma unroll
        for (int u = 0; u < PF; ++u) {
            float2 evn = s_ev[e + u + PF];
            float d = dbuf[u], w = wbuf[u];
            dbuf[u] = evn.x;
            wbuf[u] = *(const float*)(w1b + __float_as_int(evn.y));

            h1 = __fadd_rn(__fadd_rn(__fmul_rn(h1, d), w), bias1j);
            bool fired = valid && (h1 >= 0.5f);
            h1 = fired ? 0.0f : h1;
            unsigned m = __ballot_sync(0xffffffffu, fired);
            if (lane == 0) s_mask[(e + u) * 13 + warp] = m;
        }
    }
    __syncthreads();

    // entries per event = 1 (decay) + n_spikes
    for (int e = tid; e < EE; e += NT_A) {
        int n = 0;
        #pragma unroll
        for (int w = 0; w < 13; ++w) n += __popc(s_mask[e * 13 + w]);
        s_ent[e] = (unsigned)(1 + n);
    }
    __syncthreads();

    // exclusive prefix scan (warp 0)
    if (warp == 0) {
        unsigned run = 0;
        for (int c = 0; c < EE / 32; ++c) {
            unsigned v = s_ent[c * 32 + lane];
            unsigned sc = v;
            #pragma unroll
            for (int d = 1; d < 32; d <<= 1) {
                unsigned u = __shfl_up_sync(0xffffffffu, sc, d);
                if (lane >= d) sc += u;
            }
            s_off[c * 32 + lane] = run + sc - v;
            run += __shfl_sync(0xffffffffu, sc, 31);
        }
        if (lane == 0) *s_T = run;
    }
    __syncthreads();

    const unsigned T = *s_T;
    const unsigned Tp = (T + (CEVT - 1)) & ~(unsigned)(CEVT - 1);

    if (Tp > CAP_E) {  // effectively never
        for (int i = tid; i < EE * 13; i += NT_A)
            (&g_maskov[b][0][0])[i] = s_mask[i];
        if (tid == 0) g_tot[b] = 0xFFFFFFFFu;
        return;
    }

    float* ms = g_ms + (size_t)b * CAP_E;
    unsigned short* js = g_js + (size_t)b * CAP_E;

    for (int e = warp; e < EE; e += 13) {
        unsigned off = s_off[e];
        if (lane == 0) { ms[off] = s_d2[e]; js[off] = (unsigned short)DH; }
        unsigned m = (lane < 13) ? s_mask[e * 13 + lane] : 0u;
        int c = __popc(m);
        int sc = c;
        #pragma unroll
        for (int d = 1; d < 32; d <<= 1) {
            int v = __shfl_up_sync(0xffffffffu, sc, d);
            if (lane >= d) sc += v;
        }
        int pos = sc - c;
        unsigned base = off + 1;
        while (m) {
            int bit = __ffs(m) - 1;
            m &= m - 1;
            ms[base + pos] = 1.0f;
            js[base + pos] = (unsigned short)(lane * 32 + bit);
            ++pos;
        }
    }
    // identity padding to chunk multiple
    for (unsigned i = T + tid; i < Tp; i += NT_A) {
        ms[i] = 1.0f;
        js[i] = (unsigned short)DH;
    }
    if (tid == 0) g_tot[b] = Tp;
}

// Layer 2: one warp per sample; lanes 0..9 run the uniform FFMA chain over
// the stream, cp.async-ring-buffered 4 chunks deep.
__global__ __launch_bounds__(32) void l2_kernel(
    const float* __restrict__ times,
    float*       __restrict__ out)
{
    __shared__ float s_W2p[(DH + 1) * DOUT];
    __shared__ __align__(16) float m_ring[4][CEVT];
    __shared__ __align__(16) unsigned short j_ring[4][CEVT];

    const int b    = blockIdx.x;
    const int lane = threadIdx.x;

    for (int i = lane; i < (DH + 1) * DOUT; i += 32) s_W2p[i] = g_W2r[i];
    const unsigned tot = g_tot[b];
    __syncwarp();

    float h2 = 0.0f, cnt = 0.0f;

    if (tot == 0xFFFFFFFFu) {
        // rare fallback: direct mask scan
        const float TAUF = 0.6213349345596119f;
        if (lane < DOUT) {
            for (int e = 0; e < EE; ++e) {
                float t   = times[b * EE + e];
                float tp  = (e > 0) ? times[b * EE + e - 1] : 0.0f;
                float th  = __fadd_rn(t, 0.1f);
                float thp = (e > 0) ? __fadd_rn(tp, 0.1f) : 0.0f;
                h2 = __fmul_rn(h2, expf(__fdiv_rn(-(th - thp), TAUF)));
                for (int w = 0; w < 13; ++w) {
                    unsigned m = g_maskov[b][e][w];
                    while (m) {
                        int bit = __ffs(m) - 1;
                        m &= m - 1;
                        int j = w * 32 + bit;
                        h2 = __fadd_rn(h2, s_W2p[j * DOUT + lane]);
                        if (h2 >= 0.5f) { cnt = __fadd_rn(cnt, 1.0f); h2 = 0.0f; }
                    }
                }
            }
            out[b * DOUT + lane] = __fdiv_rn(cnt, 64.0f);
        }
        return;
    }

    const float* ms = g_ms + (size_t)b * CAP_E;
    const unsigned short* js = g_js + (size_t)b * CAP_E;
    const int NC = (int)(tot / CEVT);   // >= 16 always

    // issue one chunk's cp.asyncs (lanes 0-15: m 256B, lanes 16-23: j 128B)
    auto issue = [&](int c) {
        int rb = c & 3;
        if (lane < 16) {
            unsigned dst = (unsigned)__cvta_generic_to_shared(&m_ring[rb][0]) + lane * 16;
            const char* src = (const char*)(ms + c * CEVT) + lane * 16;
            asm volatile("cp.async.ca.shared.global [%0], [%1], 16;" :: "r"(dst), "l"(src));
        } else if (lane < 24) {
            unsigned dst = (unsigned)__cvta_generic_to_shared(&j_ring[rb][0]) + (lane - 16) * 16;
            const char* src = (const char*)(js + c * CEVT) + (lane - 16) * 16;
            asm volatile("cp.async.ca.shared.global [%0], [%1], 16;" :: "r"(dst), "l"(src));
        }
        asm volatile("cp.async.commit_group;");
    };

    issue(0); issue(1); issue(2);

    for (int c = 0; c < NC; ++c) {
        asm volatile("cp.async.wait_group 2;");
        __syncwarp();
        if (lane < DOUT) {
            const int rb = c & 3;
            for (int i = 0; i < CEVT; i += 16) {
                #pragma unroll
                for (int u = 0; u < 16; ++u) {
                    float m = m_ring[rb][i + u];
                    int   j = j_ring[rb][i + u];
                    float w = s_W2p[j * DOUT + lane];
                    h2 = __fmaf_rn(h2, m, w);       // == FMUL (a=0) / FADD (m=1)
                    bool f = h2 >= 0.5f;
                    cnt = f ? __fadd_rn(cnt, 1.0f) : cnt;
                    h2 = f ? 0.0f : h2;
                }
            }
        }
        __syncwarp();
        if (c + 3 < NC) issue(c + 3);
        else asm volatile("cp.async.commit_group;");  // keep group counts uniform
    }

    if (lane < DOUT)
        out[b * DOUT + lane] = __fdiv_rn(cnt, 64.0f);
}

extern "C" void kernel_launch(void* const* d_in, const int* in_sizes, int n_in,
                              void* d_out, int out_size) {
    const float* times = (const float*)d_in[0];  // [256,1024] f32
    const int*   pixv  = (const int*)d_in[1];    // [256,1024] i32
    const float* W1    = (const float*)d_in[2];  // [400,784]
    const float* b1    = (const float*)d_in[3];  // [400]
    const float* W2    = (const float*)d_in[4];  // [10,400]
    const float* b2    = (const float*)d_in[5];  // [10]

    cudaFuncSetAttribute(l1_kernel,
                         cudaFuncAttributeMaxDynamicSharedMemorySize, A_SMEM);

    int prep_n = DIN * DH + (DH + 1) * DOUT;
    prep_kernel<<<(prep_n + 255) / 256, 256>>>(W1, W2, b2);
    l1_kernel<<<BB, NT_A, A_SMEM>>>(times, pixv, b1);
    l2_kernel<<<BB, 32>>>(times, (float*)d_out);
}

// round 12
// speedup vs baseline: 1.0004x; 1.0004x over previous
#include <cuda_runtime.h>
#include <cuda_bf16.h>

#define EE 1024
#define BB 256
#define DIN 784
#define DH 400
#define DOUT 10
#define NT_A 416
#define PF 4
#define CAP_E 32768        // stream entries per sample (expected ~7000)
#define CEVT 64            // entries per l2 chunk

// Static device scratch (no cudaMalloc allowed)
__device__ float g_W1T[DIN * DH + 32];             // transposed W1 (+pad)
__device__ float g_W2r[(DH + 1) * DOUT];           // [401][10], row 400 = 0
__device__ float g_ms[(size_t)BB * CAP_E];         // stream: multiplier
__device__ unsigned short g_js[(size_t)BB * CAP_E];// stream: weight-row index
__device__ unsigned g_tot[BB];                     // padded stream length (or ~0 = overflow)
__device__ unsigned g_maskov[BB][EE][13];          // masks (overflow fallback only)

__global__ void prep_kernel(const float* __restrict__ W1,
                            const float* __restrict__ W2,
                            const float* __restrict__ b2) {
    int idx = blockIdx.x * blockDim.x + threadIdx.x;
    if (idx < DIN * DH) {
        int p = idx / DH;
        int j = idx - p * DH;
        g_W1T[idx] = W1[j * DIN + p];
    } else if (idx < DIN * DH + (DH + 1) * DOUT) {
        int i = idx - DIN * DH;
        int j = i / DOUT;
        int d = i - j * DOUT;
        g_W2r[i] = (j < DH)
            ? __fadd_rn(W2[d * DH + j], __fdiv_rn(b2[d], 400.0f))
            : 0.0f;
    }
}

#define A_SMEM ((EE + PF) * 8 + EE * 13 * 4 + EE * 4 * 3 + 32)

// Layer 1: one CTA/sample, 13 warps, depth-4 register prefetch, no barriers
// in main loop. Epilogue emits the uniform (m, j) FFMA stream.
__global__ __launch_bounds__(NT_A, 2) void l1_kernel(
    const float* __restrict__ times,
    const int*   __restrict__ pix,
    const float* __restrict__ b1)
{
    extern __shared__ unsigned char dyn[];
    float2*   s_ev   = (float2*)dyn;                   // [EE+PF] (decay1, byteoff)
    unsigned* s_mask = (unsigned*)(s_ev + EE + PF);    // [EE][13]
    float*    s_d2   = (float*)(s_mask + EE * 13);     // [EE]
    unsigned* s_ent  = (unsigned*)(s_d2 + EE);         // [EE] entries per event
    unsigned* s_off  = s_ent + EE;                     // [EE] exclusive prefix
    unsigned* s_T    = s_off + EE;                     // [1]

    const float TAUF = 0.6213349345596119f;  // float(-1/ln(0.2))
    const int b    = blockIdx.x;
    const int tid  = threadIdx.x;
    const int warp = tid >> 5;
    const int lane = tid & 31;

    for (int e = tid; e < EE; e += NT_A) {
        float t  = times[b * EE + e];
        float tp = (e > 0) ? times[b * EE + e - 1] : 0.0f;
        float d1 = expf(__fdiv_rn(-(t - tp), TAUF));
        float th  = __fadd_rn(t, 0.1f);
        float thp = (e > 0) ? __fadd_rn(tp, 0.1f) : 0.0f;
        s_d2[e] = expf(__fdiv_rn(-(th - thp), TAUF));
        int p = pix[b * EE + e];
        s_ev[e] = make_float2(d1, __int_as_float(p * (DH * 4)));
    }
    if (tid < PF) s_ev[EE + tid] = make_float2(1.0f, __int_as_float(0));
    __syncthreads();

    const bool valid = (tid < DH);
    float h1 = 0.0f;
    float bias1j = valid ? __fdiv_rn(b1[tid], 784.0f) : 0.0f;
    const char* w1b = (const char*)g_W1T + tid * 4;

    float wbuf[PF], dbuf[PF];
    #pragma unroll
    for (int i = 0; i < PF; ++i) {
        float2 ev = s_ev[i];
        dbuf[i] = ev.x;
        wbuf[i] = *(const float*)(w1b + __float_as_int(ev.y));
    }

    for (int e = 0; e < EE; e += PF) {
        #pragma unroll
        for (int u = 0; u < PF; ++u) {
            float2 evn = s_ev[e + u + PF];
            float d = dbuf[u], w = wbuf[u];
            dbuf[u] = evn.x;
            wbuf[u] = *(const float*)(w1b + __float_as_int(evn.y));

            h1 = __fadd_rn(__fadd_rn(__fmul_rn(h1, d), w), bias1j);
            bool fired = valid && (h1 >= 0.5f);
            h1 = fired ? 0.0f : h1;
            unsigned m = __ballot_sync(0xffffffffu, fired);
            if (lane == 0) s_mask[(e + u) * 13 + warp] = m;
        }
    }
    __syncthreads();

    // entries per event = 1 (decay) + n_spikes
    for (int e = tid; e < EE; e += NT_A) {
        int n = 0;
        #pragma unroll
        for (int w = 0; w < 13; ++w) n += __popc(s_mask[e * 13 + w]);
        s_ent[e] = (unsigned)(1 + n);
    }
    __syncthreads();

    // exclusive prefix scan (warp 0)
    if (warp == 0) {
        unsigned run = 0;
        for (int c = 0; c < EE / 32; ++c) {
            unsigned v = s_ent[c * 32 + lane];
            unsigned sc = v;
            #pragma unroll
            for (int d = 1; d < 32; d <<= 1) {
                unsigned u = __shfl_up_sync(0xffffffffu, sc, d);
                if (lane >= d) sc += u;
            }
            s_off[c * 32 + lane] = run + sc - v;
            run += __shfl_sync(0xffffffffu, sc, 31);
        }
        if (lane == 0) *s_T = run;
    }
    __syncthreads();

    const unsigned T = *s_T;
    const unsigned Tp = (T + (CEVT - 1)) & ~(unsigned)(CEVT - 1);

    if (Tp > CAP_E) {  // effectively never
        for (int i = tid; i < EE * 13; i += NT_A)
            (&g_maskov[b][0][0])[i] = s_mask[i];
        if (tid == 0) g_tot[b] = 0xFFFFFFFFu;
        return;
    }

    float* ms = g_ms + (size_t)b * CAP_E;
    unsigned short* js = g_js + (size_t)b * CAP_E;

    for (int e = warp; e < EE; e += 13) {
        unsigned off = s_off[e];
        if (lane == 0) { ms[off] = s_d2[e]; js[off] = (unsigned short)DH; }
        unsigned m = (lane < 13) ? s_mask[e * 13 + lane] : 0u;
        int c = __popc(m);
        int sc = c;
        #pragma unroll
        for (int d = 1; d < 32; d <<= 1) {
            int v = __shfl_up_sync(0xffffffffu, sc, d);
            if (lane >= d) sc += v;
        }
        int pos = sc - c;
        unsigned base = off + 1;
        while (m) {
            int bit = __ffs(m) - 1;
            m &= m - 1;
            ms[base + pos] = 1.0f;
            js[base + pos] = (unsigned short)(lane * 32 + bit);
            ++pos;
        }
    }
    // identity padding to chunk multiple
    for (unsigned i = T + tid; i < Tp; i += NT_A) {
        ms[i] = 1.0f;
        js[i] = (unsigned short)DH;
    }
    if (tid == 0) g_tot[b] = Tp;
}

// Layer 2: one warp per sample; lanes 0..9 run the uniform FFMA chain over
// the stream, cp.async-ring-buffered 4 chunks deep.
__global__ __launch_bounds__(32) void l2_kernel(
    const float* __restrict__ times,
    float*       __restrict__ out)
{
    __shared__ float s_W2p[(DH + 1) * DOUT];
    __shared__ __align__(16) float m_ring[4][CEVT];
    __shared__ __align__(16) unsigned short j_ring[4][CEVT];

    const int b    = blockIdx.x;
    const int lane = threadIdx.x;

    for (int i = lane; i < (DH + 1) * DOUT; i += 32) s_W2p[i] = g_W2r[i];
    const unsigned tot = g_tot[b];
    __syncwarp();

    float h2 = 0.0f, cnt = 0.0f;

    if (tot == 0xFFFFFFFFu) {
        // rare fallback: direct mask scan
        const float TAUF = 0.6213349345596119f;
        if (lane < DOUT) {
            for (int e = 0; e < EE; ++e) {
                float t   = times[b * EE + e];
                float tp  = (e > 0) ? times[b * EE + e - 1] : 0.0f;
                float th  = __fadd_rn(t, 0.1f);
                float thp = (e > 0) ? __fadd_rn(tp, 0.1f) : 0.0f;
                h2 = __fmul_rn(h2, expf(__fdiv_rn(-(th - thp), TAUF)));
                for (int w = 0; w < 13; ++w) {
                    unsigned m = g_maskov[b][e][w];
                    while (m) {
                        int bit = __ffs(m) - 1;
                        m &= m - 1;
                        int j = w * 32 + bit;
                        h2 = __fadd_rn(h2, s_W2p[j * DOUT + lane]);
                        if (h2 >= 0.5f) { cnt = __fadd_rn(cnt, 1.0f); h2 = 0.0f; }
                    }
                }
            }
            out[b * DOUT + lane] = __fdiv_rn(cnt, 64.0f);
        }
        return;
    }

    const float* ms = g_ms + (size_t)b * CAP_E;
    const unsigned short* js = g_js + (size_t)b * CAP_E;
    const int NC = (int)(tot / CEVT);   // >= 16 always

    // issue one chunk's cp.asyncs (lanes 0-15: m 256B, lanes 16-23: j 128B)
    auto issue = [&](int c) {
        int rb = c & 3;
        if (lane < 16) {
            unsigned dst = (unsigned)__cvta_generic_to_shared(&m_ring[rb][0]) + lane * 16;
            const char* src = (const char*)(ms + c * CEVT) + lane * 16;
            asm volatile("cp.async.ca.shared.global [%0], [%1], 16;" :: "r"(dst), "l"(src));
        } else if (lane < 24) {
            unsigned dst = (unsigned)__cvta_generic_to_shared(&j_ring[rb][0]) + (lane - 16) * 16;
            const char* src = (const char*)(js + c * CEVT) + (lane - 16) * 16;
            asm volatile("cp.async.ca.shared.global [%0], [%1], 16;" :: "r"(dst), "l"(src));
        }
        asm volatile("cp.async.commit_group;");
    };

    issue(0); issue(1); issue(2);

    for (int c = 0; c < NC; ++c) {
        asm volatile("cp.async.wait_group 2;");
        __syncwarp();
        if (lane < DOUT) {
            const int rb = c & 3;
            for (int i = 0; i < CEVT; i += 16) {
                #pragma unroll
                for (int u = 0; u < 16; ++u) {
                    float m = m_ring[rb][i + u];
                    int   j = j_ring[rb][i + u];
                    float w = s_W2p[j * DOUT + lane];
                    h2 = __fmaf_rn(h2, m, w);       // == FMUL (a=0) / FADD (m=1)
                    bool f = h2 >= 0.5f;
                    cnt = f ? __fadd_rn(cnt, 1.0f) : cnt;
                    h2 = f ? 0.0f : h2;
                }
            }
        }
        __syncwarp();
        if (c + 3 < NC) issue(c + 3);
        else asm volatile("cp.async.commit_group;");  // keep group counts uniform
    }

    if (lane < DOUT)
        out[b * DOUT + lane] = __fdiv_rn(cnt, 64.0f);
}

extern "C" void kernel_launch(void* const* d_in, const int* in_sizes, int n_in,
                              void* d_out, int out_size) {
    const float* times = (const float*)d_in[0];  // [256,1024] f32
    const int*   pixv  = (const int*)d_in[1];    // [256,1024] i32
    const float* W1    = (const float*)d_in[2];  // [400,784]
    const float* b1    = (const float*)d_in[3];  // [400]
    const float* W2    = (const float*)d_in[4];  // [10,400]
    const float* b2    = (const float*)d_in[5];  // [10]

    cudaFuncSetAttribute(l1_kernel,
                         cudaFuncAttributeMaxDynamicSharedMemorySize, A_SMEM);

    int prep_n = DIN * DH + (DH + 1) * DOUT;
    prep_kernel<<<(prep_n + 255) / 256, 256>>>(W1, W2, b2);
    l1_kernel<<<BB, NT_A, A_SMEM>>>(times, pixv, b1);
    l2_kernel<<<BB, 32>>>(times, (float*)d_out);
}

// round 13
// speedup vs baseline: 1.0017x; 1.0012x over previous
#include <cuda_runtime.h>
#include <cuda_bf16.h>

#define EE 1024
#define BB 256
#define DIN 784
#define DH 400
#define DOUT 10
#define NT_A 416
#define PF 4
#define CAP_E 32768        // stream entries per sample (expected ~7000)
#define CEVT 64            // entries per l2 chunk

// Static device scratch (no cudaMalloc allowed)
__device__ float g_W1T[DIN * DH + 32];             // transposed W1 (+pad)
__device__ float g_W2r[(DH + 1) * DOUT];           // [401][10], row 400 = 0
__device__ float g_ms[(size_t)BB * CAP_E];         // stream: multiplier
__device__ unsigned short g_js[(size_t)BB * CAP_E];// stream: weight-row index
__device__ unsigned g_tot[BB];                     // padded stream length (or ~0 = overflow)
__device__ unsigned g_maskov[BB][EE][13];          // masks (overflow fallback only)

__global__ void prep_kernel(const float* __restrict__ W1,
                            const float* __restrict__ W2,
                            const float* __restrict__ b2) {
    int idx = blockIdx.x * blockDim.x + threadIdx.x;
    if (idx < DIN * DH) {
        int p = idx / DH;
        int j = idx - p * DH;
        g_W1T[idx] = W1[j * DIN + p];
    } else if (idx < DIN * DH + (DH + 1) * DOUT) {
        int i = idx - DIN * DH;
        int j = i / DOUT;
        int d = i - j * DOUT;
        g_W2r[i] = (j < DH)
            ? __fadd_rn(W2[d * DH + j], __fdiv_rn(b2[d], 400.0f))
            : 0.0f;
    }
}

#define A_SMEM ((EE + PF) * 8 + EE * 13 * 4 + EE * 4 * 3 + 32)

// Layer 1: one CTA/sample, 13 warps, depth-4 register prefetch, no barriers
// in main loop. Epilogue emits the uniform (m, j) FFMA stream.
__global__ __launch_bounds__(NT_A, 2) void l1_kernel(
    const float* __restrict__ times,
    const int*   __restrict__ pix,
    const float* __restrict__ b1)
{
    extern __shared__ unsigned char dyn[];
    float2*   s_ev   = (float2*)dyn;                   // [EE+PF] (decay1, byteoff)
    unsigned* s_mask = (unsigned*)(s_ev + EE + PF);    // [EE][13]
    float*    s_d2   = (float*)(s_mask + EE * 13);     // [EE]
    unsigned* s_ent  = (unsigned*)(s_d2 + EE);         // [EE] entries per event
    unsigned* s_off  = s_ent + EE;                     // [EE] exclusive prefix
    unsigned* s_T    = s_off + EE;                     // [1]

    const float TAUF = 0.6213349345596119f;  // float(-1/ln(0.2))
    const int b    = blockIdx.x;
    const int tid  = threadIdx.x;
    const int warp = tid >> 5;
    const int lane = tid & 31;

    for (int e = tid; e < EE; e += NT_A) {
        float t  = times[b * EE + e];
        float tp = (e > 0) ? times[b * EE + e - 1] : 0.0f;
        float d1 = expf(__fdiv_rn(-(t - tp), TAUF));
        float th  = __fadd_rn(t, 0.1f);
        float thp = (e > 0) ? __fadd_rn(tp, 0.1f) : 0.0f;
        s_d2[e] = expf(__fdiv_rn(-(th - thp), TAUF));
        int p = pix[b * EE + e];
        s_ev[e] = make_float2(d1, __int_as_float(p * (DH * 4)));
    }
    if (tid < PF) s_ev[EE + tid] = make_float2(1.0f, __int_as_float(0));
    __syncthreads();

    const bool valid = (tid < DH);
    float h1 = 0.0f;
    float bias1j = valid ? __fdiv_rn(b1[tid], 784.0f) : 0.0f;
    const char* w1b = (const char*)g_W1T + tid * 4;

    float wbuf[PF], dbuf[PF];
    #pragma unroll
    for (int i = 0; i < PF; ++i) {
        float2 ev = s_ev[i];
        dbuf[i] = ev.x;
        wbuf[i] = *(const float*)(w1b + __float_as_int(ev.y));
    }

    for (int e = 0; e < EE; e += PF) {
        #pragma unroll
        for (int u = 0; u < PF; ++u) {
            float2 evn = s_ev[e + u + PF];
            float d = dbuf[u], w = wbuf[u];
            dbuf[u] = evn.x;
            wbuf[u] = *(const float*)(w1b + __float_as_int(evn.y));

            h1 = __fadd_rn(__fadd_rn(__fmul_rn(h1, d), w), bias1j);
            bool fired = valid && (h1 >= 0.5f);
            h1 = fired ? 0.0f : h1;
            unsigned m = __ballot_sync(0xffffffffu, fired);
            if (lane == 0) s_mask[(e + u) * 13 + warp] = m;
        }
    }
    __syncthreads();

    // entries per event = 1 (decay) + n_spikes
    for (int e = tid; e < EE; e += NT_A) {
        int n = 0;
        #pragma unroll
        for (int w = 0; w < 13; ++w) n += __popc(s_mask[e * 13 + w]);
        s_ent[e] = (unsigned)(1 + n);
    }
    __syncthreads();

    // exclusive prefix scan (warp 0)
    if (warp == 0) {
        unsigned run = 0;
        for (int c = 0; c < EE / 32; ++c) {
            unsigned v = s_ent[c * 32 + lane];
            unsigned sc = v;
            #pragma unroll
            for (int d = 1; d < 32; d <<= 1) {
                unsigned u = __shfl_up_sync(0xffffffffu, sc, d);
                if (lane >= d) sc += u;
            }
            s_off[c * 32 + lane] = run + sc - v;
            run += __shfl_sync(0xffffffffu, sc, 31);
        }
        if (lane == 0) *s_T = run;
    }
    __syncthreads();

    const unsigned T = *s_T;
    const unsigned Tp = (T + (CEVT - 1)) & ~(unsigned)(CEVT - 1);

    if (Tp > CAP_E) {  // effectively never
        for (int i = tid; i < EE * 13; i += NT_A)
            (&g_maskov[b][0][0])[i] = s_mask[i];
        if (tid == 0) g_tot[b] = 0xFFFFFFFFu;
        return;
    }

    float* ms = g_ms + (size_t)b * CAP_E;
    unsigned short* js = g_js + (size_t)b * CAP_E;

    for (int e = warp; e < EE; e += 13) {
        unsigned off = s_off[e];
        if (lane == 0) { ms[off] = s_d2[e]; js[off] = (unsigned short)DH; }
        unsigned m = (lane < 13) ? s_mask[e * 13 + lane] : 0u;
        int c = __popc(m);
        int sc = c;
        #pragma unroll
        for (int d = 1; d < 32; d <<= 1) {
            int v = __shfl_up_sync(0xffffffffu, sc, d);
            if (lane >= d) sc += v;
        }
        int pos = sc - c;
        unsigned base = off + 1;
        while (m) {
            int bit = __ffs(m) - 1;
            m &= m - 1;
            ms[base + pos] = 1.0f;
            js[base + pos] = (unsigned short)(lane * 32 + bit);
            ++pos;
        }
    }
    // identity padding to chunk multiple
    for (unsigned i = T + tid; i < Tp; i += NT_A) {
        ms[i] = 1.0f;
        js[i] = (unsigned short)DH;
    }
    if (tid == 0) g_tot[b] = Tp;
}

// Layer 2: one warp per sample; lanes 0..9 run the uniform FFMA chain over
// the stream, cp.async-ring-buffered 4 chunks deep.
__global__ __launch_bounds__(32) void l2_kernel(
    const float* __restrict__ times,
    float*       __restrict__ out)
{
    __shared__ float s_W2p[(DH + 1) * DOUT];
    __shared__ __align__(16) float m_ring[4][CEVT];
    __shared__ __align__(16) unsigned short j_ring[4][CEVT];

    const int b    = blockIdx.x;
    const int lane = threadIdx.x;

    for (int i = lane; i < (DH + 1) * DOUT; i += 32) s_W2p[i] = g_W2r[i];
    const unsigned tot = g_tot[b];
    __syncwarp();

    float h2 = 0.0f, cnt = 0.0f;

    if (tot == 0xFFFFFFFFu) {
        // rare fallback: direct mask scan
        const float TAUF = 0.6213349345596119f;
        if (lane < DOUT) {
            for (int e = 0; e < EE; ++e) {
                float t   = times[b * EE + e];
                float tp  = (e > 0) ? times[b * EE + e - 1] : 0.0f;
                float th  = __fadd_rn(t, 0.1f);
                float thp = (e > 0) ? __fadd_rn(tp, 0.1f) : 0.0f;
                h2 = __fmul_rn(h2, expf(__fdiv_rn(-(th - thp), TAUF)));
                for (int w = 0; w < 13; ++w) {
                    unsigned m = g_maskov[b][e][w];
                    while (m) {
                        int bit = __ffs(m) - 1;
                        m &= m - 1;
                        int j = w * 32 + bit;
                        h2 = __fadd_rn(h2, s_W2p[j * DOUT + lane]);
                        if (h2 >= 0.5f) { cnt = __fadd_rn(cnt, 1.0f); h2 = 0.0f; }
                    }
                }
            }
            out[b * DOUT + lane] = __fdiv_rn(cnt, 64.0f);
        }
        return;
    }

    const float* ms = g_ms + (size_t)b * CAP_E;
    const unsigned short* js = g_js + (size_t)b * CAP_E;
    const int NC = (int)(tot / CEVT);   // >= 16 always

    // issue one chunk's cp.asyncs (lanes 0-15: m 256B, lanes 16-23: j 128B)
    auto issue = [&](int c) {
        int rb = c & 3;
        if (lane < 16) {
            unsigned dst = (unsigned)__cvta_generic_to_shared(&m_ring[rb][0]) + lane * 16;
            const char* src = (const char*)(ms + c * CEVT) + lane * 16;
            asm volatile("cp.async.ca.shared.global [%0], [%1], 16;" :: "r"(dst), "l"(src));
        } else if (lane < 24) {
            unsigned dst = (unsigned)__cvta_generic_to_shared(&j_ring[rb][0]) + (lane - 16) * 16;
            const char* src = (const char*)(js + c * CEVT) + (lane - 16) * 16;
            asm volatile("cp.async.ca.shared.global [%0], [%1], 16;" :: "r"(dst), "l"(src));
        }
        asm volatile("cp.async.commit_group;");
    };

    issue(0); issue(1); issue(2);

    for (int c = 0; c < NC; ++c) {
        asm volatile("cp.async.wait_group 2;");
        __syncwarp();
        if (lane < DOUT) {
            const int rb = c & 3;
            for (int i = 0; i < CEVT; i += 16) {
                #pragma unroll
                for (int u = 0; u < 16; ++u) {
                    float m = m_ring[rb][i + u];
                    int   j = j_ring[rb][i + u];
                    float w = s_W2p[j * DOUT + lane];
                    h2 = __fmaf_rn(h2, m, w);       // == FMUL (a=0) / FADD (m=1)
                    bool f = h2 >= 0.5f;
                    cnt = f ? __fadd_rn(cnt, 1.0f) : cnt;
                    h2 = f ? 0.0f : h2;
                }
            }
        }
        __syncwarp();
        if (c + 3 < NC) issue(c + 3);
        else asm volatile("cp.async.commit_group;");  // keep group counts uniform
    }

    if (lane < DOUT)
        out[b * DOUT + lane] = __fdiv_rn(cnt, 64.0f);
}

extern "C" void kernel_launch(void* const* d_in, const int* in_sizes, int n_in,
                              void* d_out, int out_size) {
    const float* times = (const float*)d_in[0];  // [256,1024] f32
    const int*   pixv  = (const int*)d_in[1];    // [256,1024] i32
    const float* W1    = (const float*)d_in[2];  // [400,784]
    const float* b1    = (const float*)d_in[3];  // [400]
    const float* W2    = (const float*)d_in[4];  // [10,400]
    const float* b2    = (const float*)d_in[5];  // [10]

    cudaFuncSetAttribute(l1_kernel,
                         cudaFuncAttributeMaxDynamicSharedMemorySize, A_SMEM);

    int prep_n = DIN * DH + (DH + 1) * DOUT;
    prep_kernel<<<(prep_n + 255) / 256, 256>>>(W1, W2, b2);
    l1_kernel<<<BB, NT_A, A_SMEM>>>(times, pixv, b1);
    l2_kernel<<<BB, 32>>>(times, (float*)d_out);
}

// round 14
// speedup vs baseline: 1.0021x; 1.0004x over previous
#include <cuda_runtime.h>
#include <cuda_bf16.h>

#define EE 1024
#define BB 256
#define DIN 784
#define DH 400
#define DOUT 10
#define NT_A 416
#define PF 4
#define CAP_E 32768        // stream entries per sample (expected ~7000)
#define CEVT 64            // entries per l2 chunk

// Static device scratch (no cudaMalloc allowed)
__device__ float g_W1T[DIN * DH + 32];             // transposed W1 (+pad)
__device__ float g_W2r[(DH + 1) * DOUT];           // [401][10], row 400 = 0
__device__ float g_ms[(size_t)BB * CAP_E];         // stream: multiplier
__device__ unsigned short g_js[(size_t)BB * CAP_E];// stream: weight-row index
__device__ unsigned g_tot[BB];                     // padded stream length (or ~0 = overflow)
__device__ unsigned g_maskov[BB][EE][13];          // masks (overflow fallback only)

__global__ void prep_kernel(const float* __restrict__ W1,
                            const float* __restrict__ W2,
                            const float* __restrict__ b2) {
    int idx = blockIdx.x * blockDim.x + threadIdx.x;
    if (idx < DIN * DH) {
        int p = idx / DH;
        int j = idx - p * DH;
        g_W1T[idx] = W1[j * DIN + p];
    } else if (idx < DIN * DH + (DH + 1) * DOUT) {
        int i = idx - DIN * DH;
        int j = i / DOUT;
        int d = i - j * DOUT;
        g_W2r[i] = (j < DH)
            ? __fadd_rn(W2[d * DH + j], __fdiv_rn(b2[d], 400.0f))
            : 0.0f;
    }
}

#define A_SMEM ((EE + PF) * 8 + EE * 13 * 4 + EE * 4 * 3 + 32)

// Layer 1: one CTA/sample, 13 warps, depth-4 register prefetch, no barriers
// in main loop. Epilogue emits the uniform (m, j) FFMA stream.
__global__ __launch_bounds__(NT_A, 2) void l1_kernel(
    const float* __restrict__ times,
    const int*   __restrict__ pix,
    const float* __restrict__ b1)
{
    extern __shared__ unsigned char dyn[];
    float2*   s_ev   = (float2*)dyn;                   // [EE+PF] (decay1, byteoff)
    unsigned* s_mask = (unsigned*)(s_ev + EE + PF);    // [EE][13]
    float*    s_d2   = (float*)(s_mask + EE * 13);     // [EE]
    unsigned* s_ent  = (unsigned*)(s_d2 + EE);         // [EE] entries per event
    unsigned* s_off  = s_ent + EE;                     // [EE] exclusive prefix
    unsigned* s_T    = s_off + EE;                     // [1]

    const float TAUF = 0.6213349345596119f;  // float(-1/ln(0.2))
    const int b    = blockIdx.x;
    const int tid  = threadIdx.x;
    const int warp = tid >> 5;
    const int lane = tid & 31;

    for (int e = tid; e < EE; e += NT_A) {
        float t  = times[b * EE + e];
        float tp = (e > 0) ? times[b * EE + e - 1] : 0.0f;
        float d1 = expf(__fdiv_rn(-(t - tp), TAUF));
        float th  = __fadd_rn(t, 0.1f);
        float thp = (e > 0) ? __fadd_rn(tp, 0.1f) : 0.0f;
        s_d2[e] = expf(__fdiv_rn(-(th - thp), TAUF));
        int p = pix[b * EE + e];
        s_ev[e] = make_float2(d1, __int_as_float(p * (DH * 4)));
    }
    if (tid < PF) s_ev[EE + tid] = make_float2(1.0f, __int_as_float(0));
    __syncthreads();

    const bool valid = (tid < DH);
    float h1 = 0.0f;
    float bias1j = valid ? __fdiv_rn(b1[tid], 784.0f) : 0.0f;
    const char* w1b = (const char*)g_W1T + tid * 4;

    float wbuf[PF], dbuf[PF];
    #pragma unroll
    for (int i = 0; i < PF; ++i) {
        float2 ev = s_ev[i];
        dbuf[i] = ev.x;
        wbuf[i] = *(const float*)(w1b + __float_as_int(ev.y));
    }

    for (int e = 0; e < EE; e += PF) {
        #pragma unroll
        for (int u = 0; u < PF; ++u) {
            float2 evn = s_ev[e + u + PF];
            float d = dbuf[u], w = wbuf[u];
            dbuf[u] = evn.x;
            wbuf[u] = *(const float*)(w1b + __float_as_int(evn.y));

            h1 = __fadd_rn(__fadd_rn(__fmul_rn(h1, d), w), bias1j);
            bool fired = valid && (h1 >= 0.5f);
            h1 = fired ? 0.0f : h1;
            unsigned m = __ballot_sync(0xffffffffu, fired);
            if (lane == 0) s_mask[(e + u) * 13 + warp] = m;
        }
    }
    __syncthreads();

    // entries per event = 1 (decay) + n_spikes
    for (int e = tid; e < EE; e += NT_A) {
        int n = 0;
        #pragma unroll
        for (int w = 0; w < 13; ++w) n += __popc(s_mask[e * 13 + w]);
        s_ent[e] = (unsigned)(1 + n);
    }
    __syncthreads();

    // exclusive prefix scan (warp 0)
    if (warp == 0) {
        unsigned run = 0;
        for (int c = 0; c < EE / 32; ++c) {
            unsigned v = s_ent[c * 32 + lane];
            unsigned sc = v;
            #pragma unroll
            for (int d = 1; d < 32; d <<= 1) {
                unsigned u = __shfl_up_sync(0xffffffffu, sc, d);
                if (lane >= d) sc += u;
            }
            s_off[c * 32 + lane] = run + sc - v;
            run += __shfl_sync(0xffffffffu, sc, 31);
        }
        if (lane == 0) *s_T = run;
    }
    __syncthreads();

    const unsigned T = *s_T;
    const unsigned Tp = (T + (CEVT - 1)) & ~(unsigned)(CEVT - 1);

    if (Tp > CAP_E) {  // effectively never
        for (int i = tid; i < EE * 13; i += NT_A)
            (&g_maskov[b][0][0])[i] = s_mask[i];
        if (tid == 0) g_tot[b] = 0xFFFFFFFFu;
        return;
    }

    float* ms = g_ms + (size_t)b * CAP_E;
    unsigned short* js = g_js + (size_t)b * CAP_E;

    for (int e = warp; e < EE; e += 13) {
        unsigned off = s_off[e];
        if (lane == 0) { ms[off] = s_d2[e]; js[off] = (unsigned short)DH; }
        unsigned m = (lane < 13) ? s_mask[e * 13 + lane] : 0u;
        int c = __popc(m);
        int sc = c;
        #pragma unroll
        for (int d = 1; d < 32; d <<= 1) {
            int v = __shfl_up_sync(0xffffffffu, sc, d);
            if (lane >= d) sc += v;
        }
        int pos = sc - c;
        unsigned base = off + 1;
        while (m) {
            int bit = __ffs(m) - 1;
            m &= m - 1;
            ms[base + pos] = 1.0f;
            js[base + pos] = (unsigned short)(lane * 32 + bit);
            ++pos;
        }
    }
    // identity padding to chunk multiple
    for (unsigned i = T + tid; i < Tp; i += NT_A) {
        ms[i] = 1.0f;
        js[i] = (unsigned short)DH;
    }
    if (tid == 0) g_tot[b] = Tp;
}

// Layer 2: one warp per sample; lanes 0..9 run the uniform FFMA chain over
// the stream, cp.async-ring-buffered 4 chunks deep.
__global__ __launch_bounds__(32) void l2_kernel(
    const float* __restrict__ times,
    float*       __restrict__ out)
{
    __shared__ float s_W2p[(DH + 1) * DOUT];
    __shared__ __align__(16) float m_ring[4][CEVT];
    __shared__ __align__(16) unsigned short j_ring[4][CEVT];

    const int b    = blockIdx.x;
    const int lane = threadIdx.x;

    for (int i = lane; i < (DH + 1) * DOUT; i += 32) s_W2p[i] = g_W2r[i];
    const unsigned tot = g_tot[b];
    __syncwarp();

    float h2 = 0.0f, cnt = 0.0f;

    if (tot == 0xFFFFFFFFu) {
        // rare fallback: direct mask scan
        const float TAUF = 0.6213349345596119f;
        if (lane < DOUT) {
            for (int e = 0; e < EE; ++e) {
                float t   = times[b * EE + e];
                float tp  = (e > 0) ? times[b * EE + e - 1] : 0.0f;
                float th  = __fadd_rn(t, 0.1f);
                float thp = (e > 0) ? __fadd_rn(tp, 0.1f) : 0.0f;
                h2 = __fmul_rn(h2, expf(__fdiv_rn(-(th - thp), TAUF)));
                for (int w = 0; w < 13; ++w) {
                    unsigned m = g_maskov[b][e][w];
                    while (m) {
                        int bit = __ffs(m) - 1;
                        m &= m - 1;
                        int j = w * 32 + bit;
                        h2 = __fadd_rn(h2, s_W2p[j * DOUT + lane]);
                        if (h2 >= 0.5f) { cnt = __fadd_rn(cnt, 1.0f); h2 = 0.0f; }
                    }
                }
            }
            out[b * DOUT + lane] = __fdiv_rn(cnt, 64.0f);
        }
        return;
    }

    const float* ms = g_ms + (size_t)b * CAP_E;
    const unsigned short* js = g_js + (size_t)b * CAP_E;
    const int NC = (int)(tot / CEVT);   // >= 16 always

    // issue one chunk's cp.asyncs (lanes 0-15: m 256B, lanes 16-23: j 128B)
    auto issue = [&](int c) {
        int rb = c & 3;
        if (lane < 16) {
            unsigned dst = (unsigned)__cvta_generic_to_shared(&m_ring[rb][0]) + lane * 16;
            const char* src = (const char*)(ms + c * CEVT) + lane * 16;
            asm volatile("cp.async.ca.shared.global [%0], [%1], 16;" :: "r"(dst), "l"(src));
        } else if (lane < 24) {
            unsigned dst = (unsigned)__cvta_generic_to_shared(&j_ring[rb][0]) + (lane - 16) * 16;
            const char* src = (const char*)(js + c * CEVT) + (lane - 16) * 16;
            asm volatile("cp.async.ca.shared.global [%0], [%1], 16;" :: "r"(dst), "l"(src));
        }
        asm volatile("cp.async.commit_group;");
    };

    issue(0); issue(1); issue(2);

    for (int c = 0; c < NC; ++c) {
        asm volatile("cp.async.wait_group 2;");
        __syncwarp();
        if (lane < DOUT) {
            const int rb = c & 3;
            for (int i = 0; i < CEVT; i += 16) {
                #pragma unroll
                for (int u = 0; u < 16; ++u) {
                    float m = m_ring[rb][i + u];
                    int   j = j_ring[rb][i + u];
                    float w = s_W2p[j * DOUT + lane];
                    h2 = __fmaf_rn(h2, m, w);       // == FMUL (a=0) / FADD (m=1)
                    bool f = h2 >= 0.5f;
                    cnt = f ? __fadd_rn(cnt, 1.0f) : cnt;
                    h2 = f ? 0.0f : h2;
                }
            }
        }
        __syncwarp();
        if (c + 3 < NC) issue(c + 3);
        else asm volatile("cp.async.commit_group;");  // keep group counts uniform
    }

    if (lane < DOUT)
        out[b * DOUT + lane] = __fdiv_rn(cnt, 64.0f);
}

extern "C" void kernel_launch(void* const* d_in, const int* in_sizes, int n_in,
                              void* d_out, int out_size) {
    const float* times = (const float*)d_in[0];  // [256,1024] f32
    const int*   pixv  = (const int*)d_in[1];    // [256,1024] i32
    const float* W1    = (const float*)d_in[2];  // [400,784]
    const float* b1    = (const float*)d_in[3];  // [400]
    const float* W2    = (const float*)d_in[4];  // [10,400]
    const float* b2    = (const float*)d_in[5];  // [10]

    cudaFuncSetAttribute(l1_kernel,
                         cudaFuncAttributeMaxDynamicSharedMemorySize, A_SMEM);

    int prep_n = DIN * DH + (DH + 1) * DOUT;
    prep_kernel<<<(prep_n + 255) / 256, 256>>>(W1, W2, b2);
    l1_kernel<<<BB, NT_A, A_SMEM>>>(times, pixv, b1);
    l2_kernel<<<BB, 32>>>(times, (float*)d_out);
}